// round 10
// baseline (speedup 1.0000x reference)
#include <cuda_runtime.h>
#include <cuda_fp16.h>
#include <mma.h>

using namespace nvcuda;

// Problem constants (fixed by the dataset)
#define NN   50000
#define EE   800000
#define D1   128
#define HH   4
#define CC1  32
#define DOUT 32
#define SLOPE 0.2f
#define NCH  ((NN + 1023) / 1024)   // 49 scan chunks

// ---------------- scratch (static device arrays: no allocation) -------------
__device__ int     g_deg[NN];        // zero at load; re-zeroed by k_scan1 each run
__device__ int     g_off[NN + 1];    // CHUNK-LOCAL exclusive offsets (+ total at [NN])
__device__ int     g_rank[EE];
__device__ int     g_part[64];       // per-chunk totals
__device__ int     g_ssrc[EE];       // edges only; self loops implicit
__device__ __align__(16) __half2 g_xp1h[NN * 64];
__device__ __align__(16) __half  g_hh[NN * D1];
__device__ __align__(16) __half  g_xp2h[NN * DOUT];
__device__ float   g_as1[NN * HH];
__device__ float   g_ad1[NN * HH];
__device__ float   g_as2[NN];
__device__ float   g_ad2[NN];

__device__ __forceinline__ float leaky(float v) { return v > 0.f ? v : SLOPE * v; }

// redundant per-block exclusive scan of the 49 chunk totals (1 warp, pair trick)
__device__ __forceinline__ void base_scan(int* sb) {
    int t = threadIdx.x;
    if (t < 32) {
        int v0 = (2 * t < NCH)     ? g_part[2 * t]     : 0;
        int v1 = (2 * t + 1 < NCH) ? g_part[2 * t + 1] : 0;
        int s = v0 + v1;
        int q = s;
        #pragma unroll
        for (int d = 1; d < 32; d <<= 1) {
            int y = __shfl_up_sync(0xffffffffu, q, d);
            if (t >= d) q += y;
        }
        sb[2 * t]     = q - s;
        sb[2 * t + 1] = q - s + v0;
    }
    __syncthreads();
}

// ---------------- CSR build (3 kernels) -------------------------------------
__global__ void k_rank(const int* __restrict__ dst) {
    int e4 = blockIdx.x * blockDim.x + threadIdx.x;
    if (e4 < EE / 4) {
        int4 d = ((const int4*)dst)[e4];
        int4 r;
        r.x = atomicAdd(&g_deg[d.x], 1);
        r.y = atomicAdd(&g_deg[d.y], 1);
        r.z = atomicAdd(&g_deg[d.z], 1);
        r.w = atomicAdd(&g_deg[d.w], 1);
        ((int4*)g_rank)[e4] = r;
    }
}

__global__ void __launch_bounds__(1024) k_scan1() {  // grid = NCH
    __shared__ int s[1024];
    int t = threadIdx.x;
    int i = blockIdx.x * 1024 + t;
    int v = 0;
    if (i < NN) {
        v = g_deg[i];        // real edges only (self loops implicit)
        g_deg[i] = 0;        // reset for next replay (deterministic)
    }
    s[t] = v;
    __syncthreads();
    #pragma unroll
    for (int d = 1; d < 1024; d <<= 1) {
        int x = (t >= d) ? s[t - d] : 0;
        __syncthreads();
        s[t] += x;
        __syncthreads();
    }
    if (i < NN) g_off[i] = s[t] - v;          // chunk-local exclusive
    if (i == NN - 1) g_off[NN] = s[t];        // chunk-local inclusive total
    if (t == 1023) g_part[blockIdx.x] = s[1023];
}

// atomic-free scatter; final slot = local_off + chunk_base + rank
__global__ void k_scatter(const int* __restrict__ ei) {
    __shared__ int sb[64];
    base_scan(sb);
    int e4 = blockIdx.x * blockDim.x + threadIdx.x;
    if (e4 < EE / 4) {
        int4 s = ((const int4*)ei)[e4];
        int4 d = ((const int4*)(ei + EE))[e4];
        int4 r = ((const int4*)g_rank)[e4];
        g_ssrc[g_off[d.x] + sb[d.x >> 10] + r.x] = s.x;
        g_ssrc[g_off[d.y] + sb[d.y >> 10] + r.y] = s.y;
        g_ssrc[g_off[d.z] + sb[d.z >> 10] + r.z] = s.z;
        g_ssrc[g_off[d.w] + sb[d.w >> 10] + r.w] = s.w;
    }
}

// ---- GEMM1 (tensor cores): xp1 = x @ W1, fp16 in / fp32 acc ---------------
#define GA_LD 136
#define GA_ABYTES (64 * GA_LD * 2)
#define GA_BBYTES (128 * GA_LD * 2)
#define GA_SMEM   (GA_ABYTES + GA_BBYTES)
#define GC_LD 132

__global__ void __launch_bounds__(256)
k_gemm1(const float* __restrict__ x, const float* __restrict__ W,
        const float* __restrict__ asrc, const float* __restrict__ adst) {
    extern __shared__ char smem_raw[];
    __half* Ah = (__half*)smem_raw;
    __half* Bh = (__half*)(smem_raw + GA_ABYTES);
    float*  Cf = (float*)smem_raw;               // reused after mainloop

    int t = threadIdx.x;
    int lane = t & 31;
    int warp = t >> 5;
    int row0 = blockIdx.x * 64;
    int wm = warp >> 2;
    int wn = warp & 3;

    #pragma unroll
    for (int i = 0; i < 8; i++) {
        int idx = t + i * 256;
        int row = idx >> 5;
        int c4 = (idx & 31) * 4;
        int grow = row0 + row;
        float4 v = (grow < NN) ? *(const float4*)(x + grow * 128 + c4)
                               : make_float4(0, 0, 0, 0);
        __half* p = Ah + row * GA_LD + c4;
        p[0] = __float2half_rn(v.x); p[1] = __float2half_rn(v.y);
        p[2] = __float2half_rn(v.z); p[3] = __float2half_rn(v.w);
    }
    #pragma unroll
    for (int i = 0; i < 16; i++) {
        int idx = t + i * 256;
        int row = idx >> 5;
        int c4 = (idx & 31) * 4;
        float4 v = *(const float4*)(W + row * 128 + c4);
        __half* p = Bh + row * GA_LD + c4;
        p[0] = __float2half_rn(v.x); p[1] = __float2half_rn(v.y);
        p[2] = __float2half_rn(v.z); p[3] = __float2half_rn(v.w);
    }
    __syncthreads();

    wmma::fragment<wmma::accumulator, 16, 16, 16, float> c[2][2];
    #pragma unroll
    for (int i = 0; i < 2; i++)
        #pragma unroll
        for (int j = 0; j < 2; j++)
            wmma::fill_fragment(c[i][j], 0.0f);

    #pragma unroll
    for (int k0 = 0; k0 < 128; k0 += 16) {
        wmma::fragment<wmma::matrix_a, 16, 16, 16, __half, wmma::row_major> a[2];
        wmma::fragment<wmma::matrix_b, 16, 16, 16, __half, wmma::row_major> b[2];
        #pragma unroll
        for (int i = 0; i < 2; i++)
            wmma::load_matrix_sync(a[i], Ah + (wm * 32 + i * 16) * GA_LD + k0, GA_LD);
        #pragma unroll
        for (int j = 0; j < 2; j++)
            wmma::load_matrix_sync(b[j], Bh + k0 * GA_LD + wn * 32 + j * 16, GA_LD);
        #pragma unroll
        for (int i = 0; i < 2; i++)
            #pragma unroll
            for (int j = 0; j < 2; j++)
                wmma::mma_sync(c[i][j], a[i], b[j], c[i][j]);
    }
    __syncthreads();

    #pragma unroll
    for (int i = 0; i < 2; i++)
        #pragma unroll
        for (int j = 0; j < 2; j++)
            wmma::store_matrix_sync(Cf + (wm * 32 + i * 16) * GC_LD + wn * 32 + j * 16,
                                    c[i][j], GC_LD, wmma::mem_row_major);
    __syncthreads();

    int c0 = lane * 4;
    float4 asv = *(const float4*)(asrc + c0);
    float4 adv = *(const float4*)(adst + c0);
    int h = lane >> 3;
    #pragma unroll
    for (int rr = 0; rr < 8; rr++) {
        int row = warp * 8 + rr;
        int grow = row0 + row;
        float4 v = *(const float4*)(Cf + row * GC_LD + c0);
        if (grow < NN) {
            __half2 h0 = __floats2half2_rn(v.x, v.y);
            __half2 h1 = __floats2half2_rn(v.z, v.w);
            uint2 pk;
            pk.x = *(unsigned*)&h0;
            pk.y = *(unsigned*)&h1;
            *(uint2*)(g_xp1h + grow * 64 + lane * 2) = pk;
        }
        float ps = v.x * asv.x + v.y * asv.y + v.z * asv.z + v.w * asv.w;
        float pd = v.x * adv.x + v.y * adv.y + v.z * adv.z + v.w * adv.w;
        #pragma unroll
        for (int o = 1; o < 8; o <<= 1) {
            ps += __shfl_xor_sync(0xffffffffu, ps, o);
            pd += __shfl_xor_sync(0xffffffffu, pd, o);
        }
        if ((lane & 7) == 0 && grow < NN) {
            g_as1[grow * 4 + h] = ps;
            g_ad1[grow * 4 + h] = pd;
        }
    }
}

// ---- layer-1 aggregation: warp/node, implicit self loop --------------------
__global__ void __launch_bounds__(256) k_agg1(const float* __restrict__ b1) {
    __shared__ int sb[64];
    base_scan(sb);
    int gw = (blockIdx.x * blockDim.x + threadIdx.x) >> 5;
    int lane = threadIdx.x & 31;
    if (gw >= NN) return;
    int i = gw;
    int s0 = g_off[i]     + sb[i >> 10];
    int s1 = g_off[i + 1] + sb[(i + 1) >> 10];
    int myhead = lane >> 3;          // weight-compute role: head
    int es = lane & 7;               // weight-compute role: edge slot
    int h4 = lane >> 4;              // gather role: edge parity
    int lane15 = lane & 15;          // gather role: channel group (8 ch)
    int wbase = (lane & 12) << 1;    // lane base holding my gather-head's weights
    float adh = g_ad1[i * 4 + myhead];

    // self contribution (implicit self loop)
    float denl = (es == 0) ? __expf(leaky(g_as1[i * 4 + myhead] + adh)) : 0.f;
    float acc[8];
    #pragma unroll
    for (int k = 0; k < 8; k++) acc[k] = 0.f;
    if (h4 == 0) {
        int hh2 = lane15 >> 2;       // head covering my channel group
        float wself = __expf(leaky(g_as1[i * 4 + hh2] + g_ad1[i * 4 + hh2]));
        uint4 p = *(const uint4*)(g_xp1h + i * 64 + lane15 * 4);
        float2 v0 = __half22float2(*(__half2*)&p.x);
        float2 v1 = __half22float2(*(__half2*)&p.y);
        float2 v2 = __half22float2(*(__half2*)&p.z);
        float2 v3 = __half22float2(*(__half2*)&p.w);
        acc[0] = wself * v0.x; acc[1] = wself * v0.y;
        acc[2] = wself * v1.x; acc[3] = wself * v1.y;
        acc[4] = wself * v2.x; acc[5] = wself * v2.y;
        acc[6] = wself * v3.x; acc[7] = wself * v3.y;
    }

    for (int base = s0; base < s1; base += 8) {
        int n = s1 - base; if (n > 8) n = 8;
        int src_l = i;
        float w_l = 0.f;
        if (es < n) {
            src_l = g_ssrc[base + es];
            w_l = __expf(leaky(g_as1[src_l * 4 + myhead] + adh));
        }
        denl += w_l;
        int npair = (n + 1) >> 1;
        for (int j = 0; j < npair; j++) {
            int slot = 2 * j + h4;
            int src = __shfl_sync(0xffffffffu, src_l, slot);
            float wv = __shfl_sync(0xffffffffu, w_l, wbase + slot);
            if (slot < n) {
                uint4 p = *(const uint4*)(g_xp1h + src * 64 + lane15 * 4);
                float2 v0 = __half22float2(*(__half2*)&p.x);
                float2 v1 = __half22float2(*(__half2*)&p.y);
                float2 v2 = __half22float2(*(__half2*)&p.z);
                float2 v3 = __half22float2(*(__half2*)&p.w);
                acc[0] = fmaf(wv, v0.x, acc[0]); acc[1] = fmaf(wv, v0.y, acc[1]);
                acc[2] = fmaf(wv, v1.x, acc[2]); acc[3] = fmaf(wv, v1.y, acc[3]);
                acc[4] = fmaf(wv, v2.x, acc[4]); acc[5] = fmaf(wv, v2.y, acc[5]);
                acc[6] = fmaf(wv, v3.x, acc[6]); acc[7] = fmaf(wv, v3.y, acc[7]);
            }
        }
    }
    // per-head denominators (8-lane groups), broadcast to gather lanes
    denl += __shfl_xor_sync(0xffffffffu, denl, 1);
    denl += __shfl_xor_sync(0xffffffffu, denl, 2);
    denl += __shfl_xor_sync(0xffffffffu, denl, 4);
    float denv = __shfl_sync(0xffffffffu, denl, wbase);
    float inv = 1.0f / denv;
    // combine the two edge-parity halves
    #pragma unroll
    for (int k = 0; k < 8; k++)
        acc[k] += __shfl_xor_sync(0xffffffffu, acc[k], 16);
    // bias + relu + fp16 store (lanes 0-15 cover all 128 channels)
    int ch0 = lane15 * 8;
    float4 bb0 = *(const float4*)(b1 + ch0);
    float4 bb1 = *(const float4*)(b1 + ch0 + 4);
    __half hv[8];
    hv[0] = __float2half_rn(fmaxf(fmaf(acc[0], inv, bb0.x), 0.f));
    hv[1] = __float2half_rn(fmaxf(fmaf(acc[1], inv, bb0.y), 0.f));
    hv[2] = __float2half_rn(fmaxf(fmaf(acc[2], inv, bb0.z), 0.f));
    hv[3] = __float2half_rn(fmaxf(fmaf(acc[3], inv, bb0.w), 0.f));
    hv[4] = __float2half_rn(fmaxf(fmaf(acc[4], inv, bb1.x), 0.f));
    hv[5] = __float2half_rn(fmaxf(fmaf(acc[5], inv, bb1.y), 0.f));
    hv[6] = __float2half_rn(fmaxf(fmaf(acc[6], inv, bb1.z), 0.f));
    hv[7] = __float2half_rn(fmaxf(fmaf(acc[7], inv, bb1.w), 0.f));
    if (h4 == 0)
        *(uint4*)(g_hh + i * 128 + ch0) = *(uint4*)hv;
}

// ---- GEMM2 (tensor cores): xp2 = h @ W2 + fused attention dots -------------
#define G2_ALD 136
#define G2_BLD 40
#define G2_CLD 36

__global__ void __launch_bounds__(256)
k_gemm2(const float* __restrict__ W2,
        const float* __restrict__ asrc, const float* __restrict__ adst) {
    __shared__ __half Ah[128 * G2_ALD];
    __shared__ __half Bh[128 * G2_BLD];
    float* Cf = (float*)Ah;

    int t = threadIdx.x;
    int warp = t >> 5;
    int row0 = blockIdx.x * 128;

    #pragma unroll
    for (int i = 0; i < 8; i++) {
        int idx = t + i * 256;
        int row = idx >> 4;
        int q = idx & 15;
        int grow = row0 + row;
        uint4 v = (grow < NN) ? *(const uint4*)(g_hh + grow * 128 + q * 8)
                              : make_uint4(0, 0, 0, 0);
        *(uint4*)(Ah + row * G2_ALD + q * 8) = v;
    }
    #pragma unroll
    for (int i = 0; i < 4; i++) {
        int idx = t + i * 256;
        int row = idx >> 3;
        int c4 = (idx & 7) * 4;
        float4 v = *(const float4*)(W2 + row * 32 + c4);
        __half* p = Bh + row * G2_BLD + c4;
        p[0] = __float2half_rn(v.x); p[1] = __float2half_rn(v.y);
        p[2] = __float2half_rn(v.z); p[3] = __float2half_rn(v.w);
    }
    __syncthreads();

    wmma::fragment<wmma::accumulator, 16, 16, 16, float> c[2];
    wmma::fill_fragment(c[0], 0.0f);
    wmma::fill_fragment(c[1], 0.0f);

    #pragma unroll
    for (int k0 = 0; k0 < 128; k0 += 16) {
        wmma::fragment<wmma::matrix_a, 16, 16, 16, __half, wmma::row_major> a;
        wmma::fragment<wmma::matrix_b, 16, 16, 16, __half, wmma::row_major> b[2];
        wmma::load_matrix_sync(a, Ah + (warp * 16) * G2_ALD + k0, G2_ALD);
        wmma::load_matrix_sync(b[0], Bh + k0 * G2_BLD + 0, G2_BLD);
        wmma::load_matrix_sync(b[1], Bh + k0 * G2_BLD + 16, G2_BLD);
        wmma::mma_sync(c[0], a, b[0], c[0]);
        wmma::mma_sync(c[1], a, b[1], c[1]);
    }
    __syncthreads();

    wmma::store_matrix_sync(Cf + (warp * 16) * G2_CLD + 0,  c[0], G2_CLD,
                            wmma::mem_row_major);
    wmma::store_matrix_sync(Cf + (warp * 16) * G2_CLD + 16, c[1], G2_CLD,
                            wmma::mem_row_major);
    __syncthreads();

    int row = t >> 1;
    int c0 = (t & 1) * 16;
    int grow = row0 + row;
    float v[16];
    #pragma unroll
    for (int j = 0; j < 16; j++) v[j] = Cf[row * G2_CLD + c0 + j];

    float ps = 0.f, pd = 0.f;
    #pragma unroll
    for (int j = 0; j < 16; j++) {
        ps = fmaf(v[j], asrc[c0 + j], ps);
        pd = fmaf(v[j], adst[c0 + j], pd);
    }
    ps += __shfl_xor_sync(0xffffffffu, ps, 1);
    pd += __shfl_xor_sync(0xffffffffu, pd, 1);

    if (grow < NN) {
        __half hv[16];
        #pragma unroll
        for (int j = 0; j < 16; j++) hv[j] = __float2half_rn(v[j]);
        *(uint4*)(g_xp2h + grow * 32 + c0)     = *(uint4*)&hv[0];
        *(uint4*)(g_xp2h + grow * 32 + c0 + 8) = *(uint4*)&hv[8];
        if ((t & 1) == 0) {
            g_as2[grow] = ps;
            g_ad2[grow] = pd;
        }
    }
}

// ---- layer-2 aggregation: warp/node, implicit self loop --------------------
__global__ void __launch_bounds__(256)
k_agg2(const float* __restrict__ b2, float* __restrict__ out) {
    __shared__ int sb[64];
    base_scan(sb);
    int gw = (blockIdx.x * blockDim.x + threadIdx.x) >> 5;
    int lane = threadIdx.x & 31;
    if (gw >= NN) return;
    int i = gw;
    int s0 = g_off[i]     + sb[i >> 10];
    int s1 = g_off[i + 1] + sb[(i + 1) >> 10];
    float ad = g_ad2[i];
    int q4 = lane >> 2;       // gather role: edge sub-slot 0..7
    int cg = lane & 3;        // gather role: channel group (8 halves)

    // self contribution (implicit self loop)
    float wself = __expf(leaky(g_as2[i] + ad));
    float den = (lane == 0) ? wself : 0.f;
    float acc[8];
    #pragma unroll
    for (int k = 0; k < 8; k++) acc[k] = 0.f;
    if (q4 == 0) {
        uint4 p = *(const uint4*)(g_xp2h + i * 32 + cg * 8);
        float2 v0 = __half22float2(*(__half2*)&p.x);
        float2 v1 = __half22float2(*(__half2*)&p.y);
        float2 v2 = __half22float2(*(__half2*)&p.z);
        float2 v3 = __half22float2(*(__half2*)&p.w);
        acc[0] = wself * v0.x; acc[1] = wself * v0.y;
        acc[2] = wself * v1.x; acc[3] = wself * v1.y;
        acc[4] = wself * v2.x; acc[5] = wself * v2.y;
        acc[6] = wself * v3.x; acc[7] = wself * v3.y;
    }

    for (int base = s0; base < s1; base += 32) {
        int n = s1 - base; if (n > 32) n = 32;
        int src_l = i;
        float w_l = 0.f;
        if (lane < n) {
            src_l = g_ssrc[base + lane];
            w_l = __expf(leaky(g_as2[src_l] + ad));
        }
        den += w_l;
        int niter = (n + 7) >> 3;
        for (int j = 0; j < niter; j++) {
            int slot = 8 * j + q4;
            int src = __shfl_sync(0xffffffffu, src_l, slot);
            float wv = __shfl_sync(0xffffffffu, w_l, slot);
            if (slot < n) {
                uint4 p = *(const uint4*)(g_xp2h + src * 32 + cg * 8);
                float2 v0 = __half22float2(*(__half2*)&p.x);
                float2 v1 = __half22float2(*(__half2*)&p.y);
                float2 v2 = __half22float2(*(__half2*)&p.z);
                float2 v3 = __half22float2(*(__half2*)&p.w);
                acc[0] = fmaf(wv, v0.x, acc[0]); acc[1] = fmaf(wv, v0.y, acc[1]);
                acc[2] = fmaf(wv, v1.x, acc[2]); acc[3] = fmaf(wv, v1.y, acc[3]);
                acc[4] = fmaf(wv, v2.x, acc[4]); acc[5] = fmaf(wv, v2.y, acc[5]);
                acc[6] = fmaf(wv, v3.x, acc[6]); acc[7] = fmaf(wv, v3.y, acc[7]);
            }
        }
    }
    #pragma unroll
    for (int o = 16; o; o >>= 1)
        den += __shfl_xor_sync(0xffffffffu, den, o);
    #pragma unroll
    for (int k = 0; k < 8; k++) {
        acc[k] += __shfl_xor_sync(0xffffffffu, acc[k], 4);
        acc[k] += __shfl_xor_sync(0xffffffffu, acc[k], 8);
        acc[k] += __shfl_xor_sync(0xffffffffu, acc[k], 16);
    }
    float inv = 1.0f / den;
    if (lane < 4) {
        int ch0 = cg * 8;
        float4 o0, o1;
        o0.x = fmaf(acc[0], inv, b2[ch0 + 0]);
        o0.y = fmaf(acc[1], inv, b2[ch0 + 1]);
        o0.z = fmaf(acc[2], inv, b2[ch0 + 2]);
        o0.w = fmaf(acc[3], inv, b2[ch0 + 3]);
        o1.x = fmaf(acc[4], inv, b2[ch0 + 4]);
        o1.y = fmaf(acc[5], inv, b2[ch0 + 5]);
        o1.z = fmaf(acc[6], inv, b2[ch0 + 6]);
        o1.w = fmaf(acc[7], inv, b2[ch0 + 7]);
        *(float4*)(out + i * 32 + ch0)     = o0;
        *(float4*)(out + i * 32 + ch0 + 4) = o1;
    }
}

// ---------------- launch ----------------------------------------------------
extern "C" void kernel_launch(void* const* d_in, const int* in_sizes, int n_in,
                              void* d_out, int out_size) {
    const float* x   = (const float*)d_in[0];
    const int*   ei  = (const int*)  d_in[1];
    const float* W1  = (const float*)d_in[2];
    const float* as1 = (const float*)d_in[3];
    const float* ad1 = (const float*)d_in[4];
    const float* b1  = (const float*)d_in[5];
    const float* W2  = (const float*)d_in[6];
    const float* as2 = (const float*)d_in[7];
    const float* ad2 = (const float*)d_in[8];
    const float* b2  = (const float*)d_in[9];
    float* out = (float*)d_out;

    const int nblkE4 = (EE / 4 + 255) / 256;
    const int nblkW  = (NN * 32 + 255) / 256;   // one warp per node

    static bool init_done = false;
    static cudaStream_t s2 = 0;
    static cudaEvent_t evF = 0, evJ = 0;
    if (!init_done) {
        cudaFuncSetAttribute(k_gemm1, cudaFuncAttributeMaxDynamicSharedMemorySize,
                             GA_SMEM);
        cudaStream_t st;
        if (cudaStreamCreateWithFlags(&st, cudaStreamNonBlocking) == cudaSuccess &&
            cudaEventCreateWithFlags(&evF, cudaEventDisableTiming) == cudaSuccess &&
            cudaEventCreateWithFlags(&evJ, cudaEventDisableTiming) == cudaSuccess) {
            s2 = st;
        } else {
            s2 = 0;
        }
        init_done = true;
    }

    // fork GEMM1 (independent of CSR build) onto second stream
    if (s2) {
        cudaEventRecord(evF, 0);
        cudaStreamWaitEvent(s2, evF, 0);
        k_gemm1<<<(NN + 63) / 64, 256, GA_SMEM, s2>>>(x, W1, as1, ad1);
        cudaEventRecord(evJ, s2);
    }

    // CSR build on stream 0 (3 launches)
    k_rank<<<nblkE4, 256>>>(ei + EE);
    k_scan1<<<NCH, 1024>>>();
    k_scatter<<<nblkE4, 256>>>(ei);

    if (s2) {
        cudaStreamWaitEvent(0, evJ, 0);
    } else {
        k_gemm1<<<(NN + 63) / 64, 256, GA_SMEM>>>(x, W1, as1, ad1);
    }

    k_agg1<<<nblkW, 256>>>(b1);
    k_gemm2<<<(NN + 127) / 128, 256>>>(W2, as2, ad2);
    k_agg2<<<nblkW, 256>>>(b2, out);
}

// round 11
// speedup vs baseline: 1.1388x; 1.1388x over previous
#include <cuda_runtime.h>
#include <cuda_fp16.h>
#include <mma.h>

using namespace nvcuda;

// Problem constants (fixed by the dataset)
#define NN   50000
#define EE   800000
#define D1   128
#define HH   4
#define CC1  32
#define DOUT 32
#define SLOPE 0.2f
#define SMAX 128          // per-node bucket capacity (avg deg 16; overflow ~impossible)

// ---------------- scratch (static device arrays: no allocation) -------------
__device__ int     g_deg[NN];        // zero at load; reset by k_agg2 each run
__device__ int     g_spad[NN * SMAX];// padded per-dst source buckets
__device__ __align__(16) __half2 g_xp1h[NN * 64];
__device__ __align__(16) __half  g_hh[NN * D1];
__device__ __align__(16) __half  g_xp2h[NN * DOUT];
__device__ float   g_as1[NN * HH];
__device__ float   g_ad1[NN * HH];
__device__ float   g_as2[NN];
__device__ float   g_ad2[NN];

__device__ __forceinline__ float leaky(float v) { return v > 0.f ? v : SLOPE * v; }

// ---- fused rank+scatter: ONE kernel builds the whole adjacency -------------
__global__ void k_bucket(const int* __restrict__ ei) {
    int e4 = blockIdx.x * blockDim.x + threadIdx.x;
    if (e4 < EE / 4) {
        int4 s = ((const int4*)ei)[e4];
        int4 d = ((const int4*)(ei + EE))[e4];
        int r;
        r = atomicAdd(&g_deg[d.x], 1); if (r < SMAX) g_spad[d.x * SMAX + r] = s.x;
        r = atomicAdd(&g_deg[d.y], 1); if (r < SMAX) g_spad[d.y * SMAX + r] = s.y;
        r = atomicAdd(&g_deg[d.z], 1); if (r < SMAX) g_spad[d.z * SMAX + r] = s.z;
        r = atomicAdd(&g_deg[d.w], 1); if (r < SMAX) g_spad[d.w * SMAX + r] = s.w;
    }
}

// ---- GEMM1 (tensor cores): xp1 = x @ W1, fp16 in / fp32 acc ---------------
#define GA_LD 136
#define GA_ABYTES (64 * GA_LD * 2)
#define GA_BBYTES (128 * GA_LD * 2)
#define GA_SMEM   (GA_ABYTES + GA_BBYTES)
#define GC_LD 132

__global__ void __launch_bounds__(256)
k_gemm1(const float* __restrict__ x, const float* __restrict__ W,
        const float* __restrict__ asrc, const float* __restrict__ adst) {
    extern __shared__ char smem_raw[];
    __half* Ah = (__half*)smem_raw;
    __half* Bh = (__half*)(smem_raw + GA_ABYTES);
    float*  Cf = (float*)smem_raw;               // reused after mainloop

    int t = threadIdx.x;
    int lane = t & 31;
    int warp = t >> 5;
    int row0 = blockIdx.x * 64;
    int wm = warp >> 2;
    int wn = warp & 3;

    #pragma unroll
    for (int i = 0; i < 8; i++) {
        int idx = t + i * 256;
        int row = idx >> 5;
        int c4 = (idx & 31) * 4;
        int grow = row0 + row;
        float4 v = (grow < NN) ? *(const float4*)(x + grow * 128 + c4)
                               : make_float4(0, 0, 0, 0);
        __half* p = Ah + row * GA_LD + c4;
        p[0] = __float2half_rn(v.x); p[1] = __float2half_rn(v.y);
        p[2] = __float2half_rn(v.z); p[3] = __float2half_rn(v.w);
    }
    #pragma unroll
    for (int i = 0; i < 16; i++) {
        int idx = t + i * 256;
        int row = idx >> 5;
        int c4 = (idx & 31) * 4;
        float4 v = *(const float4*)(W + row * 128 + c4);
        __half* p = Bh + row * GA_LD + c4;
        p[0] = __float2half_rn(v.x); p[1] = __float2half_rn(v.y);
        p[2] = __float2half_rn(v.z); p[3] = __float2half_rn(v.w);
    }
    __syncthreads();

    wmma::fragment<wmma::accumulator, 16, 16, 16, float> c[2][2];
    #pragma unroll
    for (int i = 0; i < 2; i++)
        #pragma unroll
        for (int j = 0; j < 2; j++)
            wmma::fill_fragment(c[i][j], 0.0f);

    #pragma unroll
    for (int k0 = 0; k0 < 128; k0 += 16) {
        wmma::fragment<wmma::matrix_a, 16, 16, 16, __half, wmma::row_major> a[2];
        wmma::fragment<wmma::matrix_b, 16, 16, 16, __half, wmma::row_major> b[2];
        #pragma unroll
        for (int i = 0; i < 2; i++)
            wmma::load_matrix_sync(a[i], Ah + (wm * 32 + i * 16) * GA_LD + k0, GA_LD);
        #pragma unroll
        for (int j = 0; j < 2; j++)
            wmma::load_matrix_sync(b[j], Bh + k0 * GA_LD + wn * 32 + j * 16, GA_LD);
        #pragma unroll
        for (int i = 0; i < 2; i++)
            #pragma unroll
            for (int j = 0; j < 2; j++)
                wmma::mma_sync(c[i][j], a[i], b[j], c[i][j]);
    }
    __syncthreads();

    #pragma unroll
    for (int i = 0; i < 2; i++)
        #pragma unroll
        for (int j = 0; j < 2; j++)
            wmma::store_matrix_sync(Cf + (wm * 32 + i * 16) * GC_LD + wn * 32 + j * 16,
                                    c[i][j], GC_LD, wmma::mem_row_major);
    __syncthreads();

    int c0 = lane * 4;
    float4 asv = *(const float4*)(asrc + c0);
    float4 adv = *(const float4*)(adst + c0);
    int h = lane >> 3;
    #pragma unroll
    for (int rr = 0; rr < 8; rr++) {
        int row = warp * 8 + rr;
        int grow = row0 + row;
        float4 v = *(const float4*)(Cf + row * GC_LD + c0);
        if (grow < NN) {
            __half2 h0 = __floats2half2_rn(v.x, v.y);
            __half2 h1 = __floats2half2_rn(v.z, v.w);
            uint2 pk;
            pk.x = *(unsigned*)&h0;
            pk.y = *(unsigned*)&h1;
            *(uint2*)(g_xp1h + grow * 64 + lane * 2) = pk;
        }
        float ps = v.x * asv.x + v.y * asv.y + v.z * asv.z + v.w * asv.w;
        float pd = v.x * adv.x + v.y * adv.y + v.z * adv.z + v.w * adv.w;
        #pragma unroll
        for (int o = 1; o < 8; o <<= 1) {
            ps += __shfl_xor_sync(0xffffffffu, ps, o);
            pd += __shfl_xor_sync(0xffffffffu, pd, o);
        }
        if ((lane & 7) == 0 && grow < NN) {
            g_as1[grow * 4 + h] = ps;
            g_ad1[grow * 4 + h] = pd;
        }
    }
}

// ---- layer-1 aggregation: warp/node, implicit self loop, bucket reads ------
__global__ void __launch_bounds__(256) k_agg1(const float* __restrict__ b1) {
    int gw = (blockIdx.x * blockDim.x + threadIdx.x) >> 5;
    int lane = threadIdx.x & 31;
    if (gw >= NN) return;
    int i = gw;
    int deg = g_deg[i]; if (deg > SMAX) deg = SMAX;
    const int* ebase = g_spad + i * SMAX;
    int myhead = lane >> 3;          // weight-compute role: head
    int es = lane & 7;               // weight-compute role: edge slot
    int h4 = lane >> 4;              // gather role: edge parity
    int lane15 = lane & 15;          // gather role: channel group (8 ch)
    int wbase = (lane & 12) << 1;    // lane base holding my gather-head's weights
    float adh = g_ad1[i * 4 + myhead];

    // self contribution (implicit self loop)
    float denl = (es == 0) ? __expf(leaky(g_as1[i * 4 + myhead] + adh)) : 0.f;
    float acc[8];
    #pragma unroll
    for (int k = 0; k < 8; k++) acc[k] = 0.f;
    if (h4 == 0) {
        int hh2 = lane15 >> 2;       // head covering my channel group
        float wself = __expf(leaky(g_as1[i * 4 + hh2] + g_ad1[i * 4 + hh2]));
        uint4 p = *(const uint4*)(g_xp1h + i * 64 + lane15 * 4);
        float2 v0 = __half22float2(*(__half2*)&p.x);
        float2 v1 = __half22float2(*(__half2*)&p.y);
        float2 v2 = __half22float2(*(__half2*)&p.z);
        float2 v3 = __half22float2(*(__half2*)&p.w);
        acc[0] = wself * v0.x; acc[1] = wself * v0.y;
        acc[2] = wself * v1.x; acc[3] = wself * v1.y;
        acc[4] = wself * v2.x; acc[5] = wself * v2.y;
        acc[6] = wself * v3.x; acc[7] = wself * v3.y;
    }

    for (int base = 0; base < deg; base += 8) {
        int n = deg - base; if (n > 8) n = 8;
        int src_l = i;
        float w_l = 0.f;
        if (es < n) {
            src_l = ebase[base + es];
            w_l = __expf(leaky(g_as1[src_l * 4 + myhead] + adh));
        }
        denl += w_l;
        int npair = (n + 1) >> 1;
        for (int j = 0; j < npair; j++) {
            int slot = 2 * j + h4;
            int src = __shfl_sync(0xffffffffu, src_l, slot);
            float wv = __shfl_sync(0xffffffffu, w_l, wbase + slot);
            if (slot < n) {
                uint4 p = *(const uint4*)(g_xp1h + src * 64 + lane15 * 4);
                float2 v0 = __half22float2(*(__half2*)&p.x);
                float2 v1 = __half22float2(*(__half2*)&p.y);
                float2 v2 = __half22float2(*(__half2*)&p.z);
                float2 v3 = __half22float2(*(__half2*)&p.w);
                acc[0] = fmaf(wv, v0.x, acc[0]); acc[1] = fmaf(wv, v0.y, acc[1]);
                acc[2] = fmaf(wv, v1.x, acc[2]); acc[3] = fmaf(wv, v1.y, acc[3]);
                acc[4] = fmaf(wv, v2.x, acc[4]); acc[5] = fmaf(wv, v2.y, acc[5]);
                acc[6] = fmaf(wv, v3.x, acc[6]); acc[7] = fmaf(wv, v3.y, acc[7]);
            }
        }
    }
    // per-head denominators (8-lane groups), broadcast to gather lanes
    denl += __shfl_xor_sync(0xffffffffu, denl, 1);
    denl += __shfl_xor_sync(0xffffffffu, denl, 2);
    denl += __shfl_xor_sync(0xffffffffu, denl, 4);
    float denv = __shfl_sync(0xffffffffu, denl, wbase);
    float inv = 1.0f / denv;
    // combine the two edge-parity halves
    #pragma unroll
    for (int k = 0; k < 8; k++)
        acc[k] += __shfl_xor_sync(0xffffffffu, acc[k], 16);
    // bias + relu + fp16 store (lanes 0-15 cover all 128 channels)
    int ch0 = lane15 * 8;
    float4 bb0 = *(const float4*)(b1 + ch0);
    float4 bb1 = *(const float4*)(b1 + ch0 + 4);
    __half hv[8];
    hv[0] = __float2half_rn(fmaxf(fmaf(acc[0], inv, bb0.x), 0.f));
    hv[1] = __float2half_rn(fmaxf(fmaf(acc[1], inv, bb0.y), 0.f));
    hv[2] = __float2half_rn(fmaxf(fmaf(acc[2], inv, bb0.z), 0.f));
    hv[3] = __float2half_rn(fmaxf(fmaf(acc[3], inv, bb0.w), 0.f));
    hv[4] = __float2half_rn(fmaxf(fmaf(acc[4], inv, bb1.x), 0.f));
    hv[5] = __float2half_rn(fmaxf(fmaf(acc[5], inv, bb1.y), 0.f));
    hv[6] = __float2half_rn(fmaxf(fmaf(acc[6], inv, bb1.z), 0.f));
    hv[7] = __float2half_rn(fmaxf(fmaf(acc[7], inv, bb1.w), 0.f));
    if (h4 == 0)
        *(uint4*)(g_hh + i * 128 + ch0) = *(uint4*)hv;
}

// ---- GEMM2 (tensor cores): xp2 = h @ W2 + fused attention dots -------------
#define G2_ALD 136
#define G2_BLD 40
#define G2_CLD 36

__global__ void __launch_bounds__(256)
k_gemm2(const float* __restrict__ W2,
        const float* __restrict__ asrc, const float* __restrict__ adst) {
    __shared__ __half Ah[128 * G2_ALD];
    __shared__ __half Bh[128 * G2_BLD];
    float* Cf = (float*)Ah;

    int t = threadIdx.x;
    int warp = t >> 5;
    int row0 = blockIdx.x * 128;

    #pragma unroll
    for (int i = 0; i < 8; i++) {
        int idx = t + i * 256;
        int row = idx >> 4;
        int q = idx & 15;
        int grow = row0 + row;
        uint4 v = (grow < NN) ? *(const uint4*)(g_hh + grow * 128 + q * 8)
                              : make_uint4(0, 0, 0, 0);
        *(uint4*)(Ah + row * G2_ALD + q * 8) = v;
    }
    #pragma unroll
    for (int i = 0; i < 4; i++) {
        int idx = t + i * 256;
        int row = idx >> 3;
        int c4 = (idx & 7) * 4;
        float4 v = *(const float4*)(W2 + row * 32 + c4);
        __half* p = Bh + row * G2_BLD + c4;
        p[0] = __float2half_rn(v.x); p[1] = __float2half_rn(v.y);
        p[2] = __float2half_rn(v.z); p[3] = __float2half_rn(v.w);
    }
    __syncthreads();

    wmma::fragment<wmma::accumulator, 16, 16, 16, float> c[2];
    wmma::fill_fragment(c[0], 0.0f);
    wmma::fill_fragment(c[1], 0.0f);

    #pragma unroll
    for (int k0 = 0; k0 < 128; k0 += 16) {
        wmma::fragment<wmma::matrix_a, 16, 16, 16, __half, wmma::row_major> a;
        wmma::fragment<wmma::matrix_b, 16, 16, 16, __half, wmma::row_major> b[2];
        wmma::load_matrix_sync(a, Ah + (warp * 16) * G2_ALD + k0, G2_ALD);
        wmma::load_matrix_sync(b[0], Bh + k0 * G2_BLD + 0, G2_BLD);
        wmma::load_matrix_sync(b[1], Bh + k0 * G2_BLD + 16, G2_BLD);
        wmma::mma_sync(c[0], a, b[0], c[0]);
        wmma::mma_sync(c[1], a, b[1], c[1]);
    }
    __syncthreads();

    wmma::store_matrix_sync(Cf + (warp * 16) * G2_CLD + 0,  c[0], G2_CLD,
                            wmma::mem_row_major);
    wmma::store_matrix_sync(Cf + (warp * 16) * G2_CLD + 16, c[1], G2_CLD,
                            wmma::mem_row_major);
    __syncthreads();

    int row = t >> 1;
    int c0 = (t & 1) * 16;
    int grow = row0 + row;
    float v[16];
    #pragma unroll
    for (int j = 0; j < 16; j++) v[j] = Cf[row * G2_CLD + c0 + j];

    float ps = 0.f, pd = 0.f;
    #pragma unroll
    for (int j = 0; j < 16; j++) {
        ps = fmaf(v[j], asrc[c0 + j], ps);
        pd = fmaf(v[j], adst[c0 + j], pd);
    }
    ps += __shfl_xor_sync(0xffffffffu, ps, 1);
    pd += __shfl_xor_sync(0xffffffffu, pd, 1);

    if (grow < NN) {
        __half hv[16];
        #pragma unroll
        for (int j = 0; j < 16; j++) hv[j] = __float2half_rn(v[j]);
        *(uint4*)(g_xp2h + grow * 32 + c0)     = *(uint4*)&hv[0];
        *(uint4*)(g_xp2h + grow * 32 + c0 + 8) = *(uint4*)&hv[8];
        if ((t & 1) == 0) {
            g_as2[grow] = ps;
            g_ad2[grow] = pd;
        }
    }
}

// ---- layer-2 aggregation: warp/node, implicit self, bucket reads, deg reset
__global__ void __launch_bounds__(256)
k_agg2(const float* __restrict__ b2, float* __restrict__ out) {
    int gw = (blockIdx.x * blockDim.x + threadIdx.x) >> 5;
    int lane = threadIdx.x & 31;
    if (gw >= NN) return;
    int i = gw;
    int deg = g_deg[i]; if (deg > SMAX) deg = SMAX;
    const int* ebase = g_spad + i * SMAX;
    float ad = g_ad2[i];
    int q4 = lane >> 2;       // gather role: edge sub-slot 0..7
    int cg = lane & 3;        // gather role: channel group (8 halves)

    // self contribution (implicit self loop)
    float wself = __expf(leaky(g_as2[i] + ad));
    float den = (lane == 0) ? wself : 0.f;
    float acc[8];
    #pragma unroll
    for (int k = 0; k < 8; k++) acc[k] = 0.f;
    if (q4 == 0) {
        uint4 p = *(const uint4*)(g_xp2h + i * 32 + cg * 8);
        float2 v0 = __half22float2(*(__half2*)&p.x);
        float2 v1 = __half22float2(*(__half2*)&p.y);
        float2 v2 = __half22float2(*(__half2*)&p.z);
        float2 v3 = __half22float2(*(__half2*)&p.w);
        acc[0] = wself * v0.x; acc[1] = wself * v0.y;
        acc[2] = wself * v1.x; acc[3] = wself * v1.y;
        acc[4] = wself * v2.x; acc[5] = wself * v2.y;
        acc[6] = wself * v3.x; acc[7] = wself * v3.y;
    }

    for (int base = 0; base < deg; base += 32) {
        int n = deg - base; if (n > 32) n = 32;
        int src_l = i;
        float w_l = 0.f;
        if (lane < n) {
            src_l = ebase[base + lane];
            w_l = __expf(leaky(g_as2[src_l] + ad));
        }
        den += w_l;
        int niter = (n + 7) >> 3;
        for (int j = 0; j < niter; j++) {
            int slot = 8 * j + q4;
            int src = __shfl_sync(0xffffffffu, src_l, slot);
            float wv = __shfl_sync(0xffffffffu, w_l, slot);
            if (slot < n) {
                uint4 p = *(const uint4*)(g_xp2h + src * 32 + cg * 8);
                float2 v0 = __half22float2(*(__half2*)&p.x);
                float2 v1 = __half22float2(*(__half2*)&p.y);
                float2 v2 = __half22float2(*(__half2*)&p.z);
                float2 v3 = __half22float2(*(__half2*)&p.w);
                acc[0] = fmaf(wv, v0.x, acc[0]); acc[1] = fmaf(wv, v0.y, acc[1]);
                acc[2] = fmaf(wv, v1.x, acc[2]); acc[3] = fmaf(wv, v1.y, acc[3]);
                acc[4] = fmaf(wv, v2.x, acc[4]); acc[5] = fmaf(wv, v2.y, acc[5]);
                acc[6] = fmaf(wv, v3.x, acc[6]); acc[7] = fmaf(wv, v3.y, acc[7]);
            }
        }
    }
    // reset degree for the next replay (deterministic rebuild)
    if (lane == 0) g_deg[i] = 0;

    #pragma unroll
    for (int o = 16; o; o >>= 1)
        den += __shfl_xor_sync(0xffffffffu, den, o);
    #pragma unroll
    for (int k = 0; k < 8; k++) {
        acc[k] += __shfl_xor_sync(0xffffffffu, acc[k], 4);
        acc[k] += __shfl_xor_sync(0xffffffffu, acc[k], 8);
        acc[k] += __shfl_xor_sync(0xffffffffu, acc[k], 16);
    }
    float inv = 1.0f / den;
    if (lane < 4) {
        int ch0 = cg * 8;
        float4 o0, o1;
        o0.x = fmaf(acc[0], inv, b2[ch0 + 0]);
        o0.y = fmaf(acc[1], inv, b2[ch0 + 1]);
        o0.z = fmaf(acc[2], inv, b2[ch0 + 2]);
        o0.w = fmaf(acc[3], inv, b2[ch0 + 3]);
        o1.x = fmaf(acc[4], inv, b2[ch0 + 4]);
        o1.y = fmaf(acc[5], inv, b2[ch0 + 5]);
        o1.z = fmaf(acc[6], inv, b2[ch0 + 6]);
        o1.w = fmaf(acc[7], inv, b2[ch0 + 7]);
        *(float4*)(out + i * 32 + ch0)     = o0;
        *(float4*)(out + i * 32 + ch0 + 4) = o1;
    }
}

// ---------------- launch ----------------------------------------------------
extern "C" void kernel_launch(void* const* d_in, const int* in_sizes, int n_in,
                              void* d_out, int out_size) {
    const float* x   = (const float*)d_in[0];
    const int*   ei  = (const int*)  d_in[1];
    const float* W1  = (const float*)d_in[2];
    const float* as1 = (const float*)d_in[3];
    const float* ad1 = (const float*)d_in[4];
    const float* b1  = (const float*)d_in[5];
    const float* W2  = (const float*)d_in[6];
    const float* as2 = (const float*)d_in[7];
    const float* ad2 = (const float*)d_in[8];
    const float* b2  = (const float*)d_in[9];
    float* out = (float*)d_out;

    const int nblkE4 = (EE / 4 + 255) / 256;
    const int nblkW  = (NN * 32 + 255) / 256;   // one warp per node

    static bool init_done = false;
    static cudaStream_t s2 = 0;
    static cudaEvent_t evF = 0, evJ = 0;
    if (!init_done) {
        cudaFuncSetAttribute(k_gemm1, cudaFuncAttributeMaxDynamicSharedMemorySize,
                             GA_SMEM);
        cudaStream_t st;
        if (cudaStreamCreateWithFlags(&st, cudaStreamNonBlocking) == cudaSuccess &&
            cudaEventCreateWithFlags(&evF, cudaEventDisableTiming) == cudaSuccess &&
            cudaEventCreateWithFlags(&evJ, cudaEventDisableTiming) == cudaSuccess) {
            s2 = st;
        } else {
            s2 = 0;
        }
        init_done = true;
    }

    // fork GEMM1 (independent of adjacency build) onto second stream
    if (s2) {
        cudaEventRecord(evF, 0);
        cudaStreamWaitEvent(s2, evF, 0);
        k_gemm1<<<(NN + 63) / 64, 256, GA_SMEM, s2>>>(x, W1, as1, ad1);
        cudaEventRecord(evJ, s2);
    }

    // adjacency build: single fused kernel (rank+scatter)
    k_bucket<<<nblkE4, 256>>>(ei);

    if (s2) {
        cudaStreamWaitEvent(0, evJ, 0);
    } else {
        k_gemm1<<<(NN + 63) / 64, 256, GA_SMEM>>>(x, W1, as1, ad1);
    }

    k_agg1<<<nblkW, 256>>>(b1);
    k_gemm2<<<(NN + 127) / 128, 256>>>(W2, as2, ad2);
    k_agg2<<<nblkW, 256>>>(b2, out);
}